// round 2
// baseline (speedup 1.0000x reference)
#include <cuda_runtime.h>
#include <math.h>

#define Bn 1024
#define Dn 512
#define Vn 128
#define Tn 201

// ---------------- device scratch (no allocations allowed) ----------------
__device__ float g_hbuf[2][Bn * Dn];   // ping-pong h
__device__ float g_c[Bn * Dn];
__device__ float g_ctx[Bn * Dn];       // time-invariant attention context
__device__ float g_E2[Vn * 4 * Dn];    // embed @ W_ih^T + b_ih + b_hh
__device__ int   g_token[Bn];

// ---------------- P1: layernorm(h0) + attention context + init ----------------
// one block per batch row; FM slab (512x49 fp32 = 100,352 B) staged in dyn smem
__global__ void k_init(const float* __restrict__ fm, const float* __restrict__ pooled,
                       const float* __restrict__ gamma, const float* __restrict__ beta,
                       const float* __restrict__ attnw, const int* __restrict__ sos) {
    extern __shared__ float dyn[];
    float* sfm = dyn;            // 25088 floats
    float* swf = dyn + 25088;    // 512 floats
    __shared__ float red[256];
    __shared__ float saw[64];
    __shared__ float sstat[2];

    int b = blockIdx.x;
    int tid = threadIdx.x;

    const float4* fmb = (const float4*)(fm + (size_t)b * 25088);
    for (int i = tid; i < 6272; i += 256) ((float4*)sfm)[i] = fmb[i];
    for (int i = tid; i < 512; i += 256) swf[i] = attnw[i];

    // ---- layernorm of pooled[b] -> h0 in g_hbuf[0]
    float x0 = pooled[b * Dn + tid];
    float x1 = pooled[b * Dn + 256 + tid];
    red[tid] = x0 + x1;
    __syncthreads();
    for (int s = 128; s > 0; s >>= 1) {
        if (tid < s) red[tid] += red[tid + s];
        __syncthreads();
    }
    if (tid == 0) sstat[0] = red[0] * (1.0f / Dn);
    __syncthreads();
    float mu = sstat[0];
    float d0 = x0 - mu, d1 = x1 - mu;
    red[tid] = d0 * d0 + d1 * d1;
    __syncthreads();
    for (int s = 128; s > 0; s >>= 1) {
        if (tid < s) red[tid] += red[tid + s];
        __syncthreads();
    }
    if (tid == 0) sstat[1] = rsqrtf(red[0] * (1.0f / Dn) + 1e-5f);
    __syncthreads();
    float rs = sstat[1];
    g_hbuf[0][b * Dn + tid]       = d0 * rs * gamma[tid]       + beta[tid];
    g_hbuf[0][b * Dn + 256 + tid] = d1 * rs * gamma[256 + tid] + beta[256 + tid];

    // ---- scores[p] = sum_d FM[b][d][p] * wf[d]   (softmax invariant to h-term)
    if (tid < 49) {
        float sc = 0.f;
        #pragma unroll 8
        for (int d = 0; d < 512; d++) sc += sfm[d * 49 + tid] * swf[d];
        saw[tid] = sc;
    }
    __syncthreads();
    if (tid == 0) {
        float mx = -1e30f;
        for (int p = 0; p < 49; p++) mx = fmaxf(mx, saw[p]);
        float sm = 0.f;
        for (int p = 0; p < 49; p++) { float e = expf(saw[p] - mx); saw[p] = e; sm += e; }
        sstat[0] = 1.0f / sm;
    }
    __syncthreads();
    float inv = sstat[0];

    // ---- context[d] = sum_p aw[p] * FM[b][d][p]; also zero c
    for (int d = tid; d < 512; d += 256) {
        float acc = 0.f;
        #pragma unroll
        for (int p = 0; p < 49; p++) acc += saw[p] * sfm[d * 49 + p];
        g_ctx[b * Dn + d] = acc * inv;
        g_c[b * Dn + d] = 0.f;
    }
    if (tid == 0) g_token[b] = *sos;
}

// ---------------- E2 = embed(128x512) @ W_ih^T(512x2048) + b_ih + b_hh ----------------
// tiled 64x64, grid (32, 2)
__global__ __launch_bounds__(256) void k_e2(const float* __restrict__ emb,
                                            const float* __restrict__ Wih,
                                            const float* __restrict__ bih,
                                            const float* __restrict__ bhh) {
    __shared__ __align__(16) float sA[16 * 68];
    __shared__ __align__(16) float sB[16 * 68];
    int m0 = blockIdx.y * 64;
    int n0 = blockIdx.x * 64;
    int tid = threadIdx.x;
    int tx = tid & 15, ty = tid >> 4;
    int lm = tid >> 2;
    int lk = (tid & 3) * 4;
    const float* Ap = emb + (size_t)(m0 + lm) * Dn + lk;
    const float* Bp = Wih + (size_t)(n0 + lm) * Dn + lk;
    float acc[4][4] = {};
    for (int kt = 0; kt < 512; kt += 16) {
        float4 a = *(const float4*)(Ap + kt);
        float4 bb = *(const float4*)(Bp + kt);
        sA[(lk + 0) * 68 + lm] = a.x;  sA[(lk + 1) * 68 + lm] = a.y;
        sA[(lk + 2) * 68 + lm] = a.z;  sA[(lk + 3) * 68 + lm] = a.w;
        sB[(lk + 0) * 68 + lm] = bb.x; sB[(lk + 1) * 68 + lm] = bb.y;
        sB[(lk + 2) * 68 + lm] = bb.z; sB[(lk + 3) * 68 + lm] = bb.w;
        __syncthreads();
        #pragma unroll
        for (int k = 0; k < 16; k++) {
            float4 av = *(const float4*)&sA[k * 68 + ty * 4];
            float4 bv = *(const float4*)&sB[k * 68 + tx * 4];
            float ar[4] = {av.x, av.y, av.z, av.w};
            float br[4] = {bv.x, bv.y, bv.z, bv.w};
            #pragma unroll
            for (int i = 0; i < 4; i++)
                #pragma unroll
                for (int j = 0; j < 4; j++) acc[i][j] += ar[i] * br[j];
        }
        __syncthreads();
    }
    int gj0 = n0 + tx * 4;
    float4 b1 = *(const float4*)&bih[gj0];
    float4 b2 = *(const float4*)&bhh[gj0];
    #pragma unroll
    for (int i = 0; i < 4; i++) {
        int gv = m0 + ty * 4 + i;
        float4 o;
        o.x = acc[i][0] + b1.x + b2.x;
        o.y = acc[i][1] + b1.y + b2.y;
        o.z = acc[i][2] + b1.z + b2.z;
        o.w = acc[i][3] + b1.w + b2.w;
        *(float4*)&g_E2[(size_t)gv * 2048 + gj0] = o;
    }
}

// ---------------- per-step: gates GEMM + fused LSTM cell ----------------
// C[b, j] = sum_k (h[b,k]+ctx[b,k]) * W_hh[j,k] + E2[token[b], j]
// N-tiling is gate-grouped: block (bx,by) owns d in [bx*16, bx*16+16) for ALL 4 gates
// (local n: gate = n>>4, dd = n&15, j = gate*512 + d0 + dd), so the LSTM cell
// fuses into the epilogue. h double-buffered by parity (hp -> hp^1).
__global__ __launch_bounds__(256) void k_gates(int hp, const float* __restrict__ Whh) {
    const float* hin = g_hbuf[hp];
    float* hout = g_hbuf[hp ^ 1];
    __shared__ __align__(16) float sA[16 * 68];
    __shared__ __align__(16) float sB[16 * 68];
    __shared__ __align__(16) float sG[64 * 64];

    int bm0 = blockIdx.y * 64;
    int d0 = blockIdx.x * 16;
    int tid = threadIdx.x;
    int tx = tid & 15, ty = tid >> 4;
    int lm = tid >> 2;
    int lk = (tid & 3) * 4;

    const float* Ap = hin + (size_t)(bm0 + lm) * Dn + lk;
    const float* Cp = g_ctx + (size_t)(bm0 + lm) * Dn + lk;
    int grow = ((lm >> 4) * 512) + d0 + (lm & 15);
    const float* Bp = Whh + (size_t)grow * Dn + lk;

    float acc[4][4] = {};
    for (int kt = 0; kt < 512; kt += 16) {
        float4 a = *(const float4*)(Ap + kt);
        float4 cx = *(const float4*)(Cp + kt);
        a.x += cx.x; a.y += cx.y; a.z += cx.z; a.w += cx.w;
        float4 bb = *(const float4*)(Bp + kt);
        sA[(lk + 0) * 68 + lm] = a.x;  sA[(lk + 1) * 68 + lm] = a.y;
        sA[(lk + 2) * 68 + lm] = a.z;  sA[(lk + 3) * 68 + lm] = a.w;
        sB[(lk + 0) * 68 + lm] = bb.x; sB[(lk + 1) * 68 + lm] = bb.y;
        sB[(lk + 2) * 68 + lm] = bb.z; sB[(lk + 3) * 68 + lm] = bb.w;
        __syncthreads();
        #pragma unroll
        for (int k = 0; k < 16; k++) {
            float4 av = *(const float4*)&sA[k * 68 + ty * 4];
            float4 bv = *(const float4*)&sB[k * 68 + tx * 4];
            float ar[4] = {av.x, av.y, av.z, av.w};
            float br[4] = {bv.x, bv.y, bv.z, bv.w};
            #pragma unroll
            for (int i = 0; i < 4; i++)
                #pragma unroll
                for (int j = 0; j < 4; j++) acc[i][j] += ar[i] * br[j];
        }
        __syncthreads();
    }

    // epilogue: add gathered E2 row, stash tile in smem for gate exchange
    int gate = tx >> 2;
    int ddb = (tx & 3) * 4;
    #pragma unroll
    for (int i = 0; i < 4; i++) {
        int gb = bm0 + ty * 4 + i;
        int tok = g_token[gb];
        float4 e = *(const float4*)&g_E2[(size_t)tok * 2048 + gate * 512 + d0 + ddb];
        float4 o;
        o.x = acc[i][0] + e.x;
        o.y = acc[i][1] + e.y;
        o.z = acc[i][2] + e.z;
        o.w = acc[i][3] + e.w;
        *(float4*)&sG[(ty * 4 + i) * 64 + tx * 4] = o;
    }
    __syncthreads();

    // fused LSTM cell: each thread handles 4 (b_local, dd) pairs
    #pragma unroll
    for (int r = 0; r < 4; r++) {
        int q = tid + 256 * r;
        int bl = q >> 4, dd = q & 15;
        float gi = sG[bl * 64 + dd];
        float gf = sG[bl * 64 + 16 + dd];
        float gg = sG[bl * 64 + 32 + dd];
        float go = sG[bl * 64 + 48 + dd];
        int idx = (bm0 + bl) * Dn + d0 + dd;
        float c = g_c[idx];
        float si = 1.f / (1.f + expf(-gi));
        float sf = 1.f / (1.f + expf(-gf));
        float so = 1.f / (1.f + expf(-go));
        float cn = sf * c + si * tanhf(gg);
        float hn = so * tanhf(cn);
        g_c[idx] = cn;
        hout[idx] = hn;
    }
}

// ---------------- per-step: logits GEMM + argmax + strided output ----------------
// block = 8 batch rows x full V=128; grid 128 blocks
__global__ __launch_bounds__(256) void k_logits(int hsel, int t,
                                                const float* __restrict__ projw,
                                                const float* __restrict__ projb,
                                                float* __restrict__ out) {
    __shared__ __align__(16) float sH[8 * 512];
    __shared__ __align__(16) float sP[16 * 132];
    __shared__ float sL[8 * 128];

    const float* h = g_hbuf[hsel];
    int b0 = blockIdx.x * 8;
    int tid = threadIdx.x;

    const float4* hsrc = (const float4*)(h + (size_t)b0 * Dn);
    for (int i = tid; i < 1024; i += 256) ((float4*)sH)[i] = hsrc[i];

    int bl = tid >> 5;   // 0..7
    int v4 = tid & 31;   // v quad
    float acc[4] = {0.f, 0.f, 0.f, 0.f};

    for (int kt = 0; kt < 512; kt += 16) {
        #pragma unroll
        for (int u = 0; u < 2; u++) {
            int f = tid * 2 + u;
            int row = f >> 2, c4 = f & 3;
            float4 p = *(const float4*)&projw[(size_t)row * Dn + kt + c4 * 4];
            sP[(c4 * 4 + 0) * 132 + row] = p.x;
            sP[(c4 * 4 + 1) * 132 + row] = p.y;
            sP[(c4 * 4 + 2) * 132 + row] = p.z;
            sP[(c4 * 4 + 3) * 132 + row] = p.w;
        }
        __syncthreads();
        #pragma unroll
        for (int k = 0; k < 16; k++) {
            float hv = sH[bl * 512 + kt + k];
            float4 pv = *(const float4*)&sP[k * 132 + v4 * 4];
            acc[0] += hv * pv.x;
            acc[1] += hv * pv.y;
            acc[2] += hv * pv.z;
            acc[3] += hv * pv.w;
        }
        __syncthreads();
    }

    int gb = b0 + bl;
    int vb = v4 * 4;
    #pragma unroll
    for (int j = 0; j < 4; j++) {
        float lg = acc[j] + projb[vb + j];
        sL[bl * 128 + vb + j] = lg;
        out[(size_t)gb * (Vn * Tn) + (size_t)(vb + j) * Tn + t] = lg;
    }
    __syncthreads();

    // argmax per batch row: warp w handles row w (first-max tiebreak like jnp.argmax)
    int w = tid >> 5, lane = tid & 31;
    float best = sL[w * 128 + lane];
    int bidx = lane;
    #pragma unroll
    for (int off = 32; off < 128; off += 32) {
        float v = sL[w * 128 + lane + off];
        if (v > best) { best = v; bidx = lane + off; }
    }
    #pragma unroll
    for (int s = 16; s > 0; s >>= 1) {
        float ov = __shfl_down_sync(0xffffffffu, best, s);
        int oi = __shfl_down_sync(0xffffffffu, bidx, s);
        if (ov > best || (ov == best && oi < bidx)) { best = ov; bidx = oi; }
    }
    if (lane == 0) g_token[b0 + w] = bidx;
}

// ---------------- launch ----------------
extern "C" void kernel_launch(void* const* d_in, const int* in_sizes, int n_in,
                              void* d_out, int out_size) {
    const float* fm     = (const float*)d_in[0];
    const float* pooled = (const float*)d_in[1];
    const float* gamma  = (const float*)d_in[2];
    const float* beta   = (const float*)d_in[3];
    const float* Wih    = (const float*)d_in[4];
    const float* Whh    = (const float*)d_in[5];
    const float* bih    = (const float*)d_in[6];
    const float* bhh    = (const float*)d_in[7];
    const float* emb    = (const float*)d_in[8];
    const float* attnw  = (const float*)d_in[9];
    // d_in[10] = attn_b: provably cancels in softmax (constant over the axis)
    const float* projw  = (const float*)d_in[11];
    const float* projb  = (const float*)d_in[12];
    const int*   sos    = (const int*)d_in[13];
    float* out = (float*)d_out;

    const int dynBytes = (25088 + 512) * 4;
    cudaFuncSetAttribute(k_init, cudaFuncAttributeMaxDynamicSharedMemorySize, dynBytes);

    k_init<<<Bn, 256, dynBytes>>>(fm, pooled, gamma, beta, attnw, sos);
    k_e2<<<dim3(32, 2), 256>>>(emb, Wih, bih, bhh);

    for (int t = 0; t < Tn; t++) {
        int hp = t & 1;
        k_gates<<<dim3(32, 16), 256>>>(hp, Whh);
        k_logits<<<128, 256>>>(hp ^ 1, t, projw, projb, out);
    }
}